// round 5
// baseline (speedup 1.0000x reference)
#include <cuda_runtime.h>
#include <cstdint>

// ---------------------------------------------------------------------------
// Problem constants
//   B=32, T=2048, C=256, H=256, STRIDE=2, TC=1024, NC1=100, NC2=90
//   FC_IN = 2*H*TC = 524288
// ---------------------------------------------------------------------------
#define TCON 1024          // TC
#define NBATCH 32
#define LSTM_SMEM ((16640 + 8704) * 4)   // sw2 + shh floats -> bytes = 101376

// ---------------------------------------------------------------------------
// Scratch (device globals; no runtime allocation allowed)
// Layouts:
//   g_y     [(t*32+b)*256 + c]        conv/bn/relu output
//   g_pre_* [(t*32+b)*1024 + g]       gate pre-activations (x-proj + bias)
//   g_h0/h1 [(t*32+b)*512 + f]        BiLSTM outputs (f: fwd 0..255, rev 256..511)
//   g_fc_part [kc][n(192)][b(32)]     FC split-k partials
// ---------------------------------------------------------------------------
__device__ float g_y[32768 * 256];
__device__ float g_pre_f[33554432];     // 32768*1024
__device__ float g_pre_r[33554432];
__device__ float g_h0[16777216];        // 32768*512
__device__ float g_h1[16777216];
__device__ float g_fc_part[32 * 192 * 32];
__device__ unsigned int g_bar_count[2];
__device__ unsigned int g_bar_gen[2];

// ---------------------------------------------------------------------------
// Helpers
// ---------------------------------------------------------------------------
__device__ __forceinline__ void fma2(unsigned long long& acc,
                                     unsigned long long a,
                                     unsigned long long b) {
    asm("fma.rn.f32x2 %0, %1, %2, %0;" : "+l"(acc) : "l"(a), "l"(b));
}
__device__ __forceinline__ float2 u2f2(unsigned long long v) {
    float2 r;
    asm("mov.b64 {%0,%1}, %2;" : "=f"(r.x), "=f"(r.y) : "l"(v));
    return r;
}
__device__ __forceinline__ float sigf(float x) {
    return __fdividef(1.f, 1.f + __expf(-x));
}
__device__ __forceinline__ float tanh_fast(float x) {
    // tanh(x) = 2*sigmoid(2x) - 1 (exact identity; __expf rel err ~1e-6)
    return 2.f * sigf(2.f * x) - 1.f;
}

// ---------------------------------------------------------------------------
// Conv1d(k=3, stride=2, pad=1) + BN(affine, eval) + ReLU
// out: g_y[(t*32+b)*256 + c]
// ---------------------------------------------------------------------------
__global__ void conv_bn(const float* __restrict__ x,
                        const float* __restrict__ cw,
                        const float* __restrict__ cb,
                        const float* __restrict__ gmm,
                        const float* __restrict__ bet,
                        const float* __restrict__ mean,
                        const float* __restrict__ var) {
    int tb = blockIdx.x;            // t*32 + b
    int t = tb >> 5, b = tb & 31;
    int c = threadIdx.x;
    float w0 = cw[c * 3 + 0], w1 = cw[c * 3 + 1], w2 = cw[c * 3 + 2];
    const float* xb = x + b * 2048;
    int xi = t * 2;
    float xm1 = (xi >= 1) ? xb[xi - 1] : 0.f;
    float x0 = xb[xi];
    float xp1 = xb[xi + 1];         // xi+1 <= 2047 always
    float conv = fmaf(xm1, w0, fmaf(x0, w1, xp1 * w2)) + cb[c];
    float inv = gmm[c] * rsqrtf(var[c] + 1e-5f);
    float v = conv * inv + (bet[c] - mean[c] * inv);
    g_y[(size_t)tb * 256 + c] = fmaxf(v, 0.f);
}

// ---------------------------------------------------------------------------
// SGEMM (TN): C[M=32768][N=1024] = A[M][K] * B[N][K]^T + bias[N]
// 128x128 block tile, BK=8, 256 threads, 8x8 micro-tile
// ---------------------------------------------------------------------------
__global__ void __launch_bounds__(256) sgemm_tn(const float* __restrict__ A,
                                                const float* __restrict__ B,
                                                const float* __restrict__ bias,
                                                float* __restrict__ C,
                                                int K) {
    __shared__ float As[8][132];
    __shared__ float Bs[8][132];
    int bm = blockIdx.y * 128;
    int bn = blockIdx.x * 128;
    int tid = threadIdx.x;
    int tx = tid & 15, ty = tid >> 4;
    int lrow = tid >> 1;
    int lk = (tid & 1) * 4;
    const float* Ap = A + (size_t)(bm + lrow) * K + lk;
    const float* Bp = B + (size_t)(bn + lrow) * K + lk;

    float acc[8][8];
#pragma unroll
    for (int i = 0; i < 8; i++)
#pragma unroll
        for (int j = 0; j < 8; j++) acc[i][j] = 0.f;

    for (int k0 = 0; k0 < K; k0 += 8) {
        float4 av = *(const float4*)(Ap + k0);
        float4 bv = *(const float4*)(Bp + k0);
        __syncthreads();
        As[lk + 0][lrow] = av.x; As[lk + 1][lrow] = av.y;
        As[lk + 2][lrow] = av.z; As[lk + 3][lrow] = av.w;
        Bs[lk + 0][lrow] = bv.x; Bs[lk + 1][lrow] = bv.y;
        Bs[lk + 2][lrow] = bv.z; Bs[lk + 3][lrow] = bv.w;
        __syncthreads();
#pragma unroll
        for (int kk = 0; kk < 8; kk++) {
            float a[8], b[8];
            *(float4*)&a[0] = *(const float4*)&As[kk][ty * 8];
            *(float4*)&a[4] = *(const float4*)&As[kk][ty * 8 + 4];
            *(float4*)&b[0] = *(const float4*)&Bs[kk][tx * 8];
            *(float4*)&b[4] = *(const float4*)&Bs[kk][tx * 8 + 4];
#pragma unroll
            for (int i = 0; i < 8; i++)
#pragma unroll
                for (int j = 0; j < 8; j++) acc[i][j] = fmaf(a[i], b[j], acc[i][j]);
        }
    }
#pragma unroll
    for (int i = 0; i < 8; i++) {
        size_t m = (size_t)(bm + ty * 8 + i);
#pragma unroll
        for (int j = 0; j < 8; j += 4) {
            int n = bn + tx * 8 + j;
            float4 o;
            o.x = acc[i][j + 0] + bias[n + 0];
            o.y = acc[i][j + 1] + bias[n + 1];
            o.z = acc[i][j + 2] + bias[n + 2];
            o.w = acc[i][j + 3] + bias[n + 3];
            *(float4*)&C[m * 1024 + n] = o;
        }
    }
}

// ---------------------------------------------------------------------------
// BiLSTM recurrence (one layer, both directions).
// 64 blocks x 128 threads. blocks [0,32): forward, [32,64): reverse.
// Block handles j in [jg*8, jg*8+8) for all 32 batches.
// Thread (jj, bb): j = jg*8+jj, batches {bb, bb+16} packed as f32x2.
// W_hh slice (32 rows x 256) resident in SMEM, duplicated (w,w) for f32x2.
// Per-step inter-block sync: atomic count + generation barrier per direction.
// ---------------------------------------------------------------------------
__global__ void __launch_bounds__(128) lstm_layer(const float* __restrict__ pre_fw,
                                                  const float* __restrict__ pre_rv,
                                                  const float* __restrict__ whh_fw,
                                                  const float* __restrict__ whh_rv,
                                                  float* __restrict__ hout) {
    extern __shared__ float smem[];
    float* sw2 = smem;              // 4 gates * 8 jj * 520 floats (duplicated pairs)
    float* shh = smem + 16640;      // 256 k * 34 (float2 (h[bb],h[bb+16]) at k*34+2bb)

    const int tid = threadIdx.x;
    const int dir = blockIdx.x >> 5;
    const int jg = blockIdx.x & 31;
    const int jj = tid >> 4;
    const int bb = tid & 15;
    const int j = jg * 8 + jj;
    const float* whh = dir ? whh_rv : whh_fw;
    const float* pre = dir ? pre_rv : pre_fw;
    const int foff = dir ? 256 : 0;

    // Load W_hh slice, duplicating each scalar into a (w,w) pair.
    for (int i = tid; i < 8192; i += 128) {
        int row = i >> 8;           // g*8 + jw  (0..31)
        int k = i & 255;
        int g = row >> 3, jw = row & 7;
        float w = whh[(g * 256 + jg * 8 + jw) * 256 + k];
        sw2[row * 520 + k * 2] = w;
        sw2[row * 520 + k * 2 + 1] = w;
    }
    for (int i = tid; i < 256 * 34; i += 128) shh[i] = 0.f;

    float cx = 0.f, cy = 0.f;
    __syncthreads();

    const float* w_i = sw2 + (0 * 8 + jj) * 520;
    const float* w_f = sw2 + (1 * 8 + jj) * 520;
    const float* w_g = sw2 + (2 * 8 + jj) * 520;
    const float* w_o = sw2 + (3 * 8 + jj) * 520;

    for (int step = 0; step < TCON; step++) {
        int t = dir ? (TCON - 1 - step) : step;
        const float* pr = pre + (size_t)t * 32 * 1024;
        // Prefetch pre-activations (consumed after the k loop -> latency hidden)
        float p_i0 = pr[bb * 1024 + j];
        float p_f0 = pr[bb * 1024 + 256 + j];
        float p_g0 = pr[bb * 1024 + 512 + j];
        float p_o0 = pr[bb * 1024 + 768 + j];
        float p_i1 = pr[(bb + 16) * 1024 + j];
        float p_f1 = pr[(bb + 16) * 1024 + 256 + j];
        float p_g1 = pr[(bb + 16) * 1024 + 512 + j];
        float p_o1 = pr[(bb + 16) * 1024 + 768 + j];

        unsigned long long ai = 0ull, af = 0ull, ag = 0ull, ao = 0ull;
#pragma unroll 2
        for (int k4 = 0; k4 < 64; k4++) {
            const float* hp = shh + (k4 * 4) * 34 + 2 * bb;
            unsigned long long h0 = *(const unsigned long long*)(hp);
            unsigned long long h1 = *(const unsigned long long*)(hp + 34);
            unsigned long long h2 = *(const unsigned long long*)(hp + 68);
            unsigned long long h3 = *(const unsigned long long*)(hp + 102);
            ulonglong2 wi0 = *(const ulonglong2*)(w_i + k4 * 8);
            ulonglong2 wi1 = *(const ulonglong2*)(w_i + k4 * 8 + 4);
            ulonglong2 wf0 = *(const ulonglong2*)(w_f + k4 * 8);
            ulonglong2 wf1 = *(const ulonglong2*)(w_f + k4 * 8 + 4);
            ulonglong2 wg0 = *(const ulonglong2*)(w_g + k4 * 8);
            ulonglong2 wg1 = *(const ulonglong2*)(w_g + k4 * 8 + 4);
            ulonglong2 wo0 = *(const ulonglong2*)(w_o + k4 * 8);
            ulonglong2 wo1 = *(const ulonglong2*)(w_o + k4 * 8 + 4);
            fma2(ai, wi0.x, h0); fma2(af, wf0.x, h0); fma2(ag, wg0.x, h0); fma2(ao, wo0.x, h0);
            fma2(ai, wi0.y, h1); fma2(af, wf0.y, h1); fma2(ag, wg0.y, h1); fma2(ao, wo0.y, h1);
            fma2(ai, wi1.x, h2); fma2(af, wf1.x, h2); fma2(ag, wg1.x, h2); fma2(ao, wo1.x, h2);
            fma2(ai, wi1.y, h3); fma2(af, wf1.y, h3); fma2(ag, wg1.y, h3); fma2(ao, wo1.y, h3);
        }

        float2 vi = u2f2(ai), vf = u2f2(af), vg = u2f2(ag), vo = u2f2(ao);
        // batch bb
        {
            float gi = vi.x + p_i0, gf = vf.x + p_f0, gg = vg.x + p_g0, go = vo.x + p_o0;
            float iv = sigf(gi), fv = sigf(gf), zv = tanh_fast(gg), ov = sigf(go);
            cx = fv * cx + iv * zv;
            float hx = ov * tanh_fast(cx);
            hout[((size_t)t * 32 + bb) * 512 + foff + j] = hx;
        }
        // batch bb+16
        {
            float gi = vi.y + p_i1, gf = vf.y + p_f1, gg = vg.y + p_g1, go = vo.y + p_o1;
            float iv = sigf(gi), fv = sigf(gf), zv = tanh_fast(gg), ov = sigf(go);
            cy = fv * cy + iv * zv;
            float hy = ov * tanh_fast(cy);
            hout[((size_t)t * 32 + bb + 16) * 512 + foff + j] = hy;
        }

        // -------- per-direction barrier (32 blocks) --------
        __syncthreads();
        if (tid == 0) {
            __threadfence();  // make our h_t stores visible
            unsigned int gen = atomicAdd(&g_bar_gen[dir], 0u);
            unsigned int old = atomicAdd(&g_bar_count[dir], 1u);
            if (old == 31u) {
                atomicExch(&g_bar_count[dir], 0u);
                __threadfence();
                atomicAdd(&g_bar_gen[dir], 1u);
            } else {
                while (atomicAdd(&g_bar_gen[dir], 0u) == gen) {}
            }
            __threadfence();  // acquire before reading others' h_t
        }
        __syncthreads();

        // Repack h_t (all 256 units, 32 batches) into shh for the next step.
        if (step < TCON - 1) {
            for (int i = tid; i < 2048; i += 128) {
                int b = i >> 6;     // 0..31
                int q = i & 63;     // float4 index along k
                float4 v = *(const float4*)&hout[((size_t)t * 32 + b) * 512 + foff + q * 4];
                int bl = (b & 15) * 2 + (b >> 4);
                shh[(q * 4 + 0) * 34 + bl] = v.x;
                shh[(q * 4 + 1) * 34 + bl] = v.y;
                shh[(q * 4 + 2) * 34 + bl] = v.z;
                shh[(q * 4 + 3) * 34 + bl] = v.w;
            }
        }
        __syncthreads();
    }
}

// ---------------------------------------------------------------------------
// FC heads: out[n][b] partials. 190 rows (100 fc1 + 90 fc2), split-k over 32
// chunks of 32 t-slabs... each chunk = 32 t x 512 f = 16384 k.
// Grid (kc=32, grp=12). Block: 16 n x (16 bb handling b, b+16).
// ---------------------------------------------------------------------------
__global__ void __launch_bounds__(256) fc_main(const float* __restrict__ h,
                                               const float* __restrict__ w1,
                                               const float* __restrict__ w2) {
    extern __shared__ float sh[];   // [512 f][32] : (f*32 + 2*bb + hi)
    int kc = blockIdx.x;            // 0..31
    int grp = blockIdx.y;           // 0..11
    int tid = threadIdx.x;
    int nl = tid >> 4, bb = tid & 15;
    int n = grp * 16 + nl;
    bool valid = (n < 190);
    const float* wrow = valid
        ? (n < 100 ? w1 + (size_t)n * 524288 : w2 + (size_t)(n - 100) * 524288)
        : w1;

    float ax = 0.f, ay = 0.f;
    for (int tt = 0; tt < 32; tt++) {
        int t = kc * 32 + tt;
        const float* slab = h + (size_t)t * 16384;   // 32 b x 512 f
        __syncthreads();
        for (int i = tid; i < 4096; i += 256) {
            int b = i >> 7;
            int q = i & 127;
            float4 v = *(const float4*)&slab[b * 512 + q * 4];
            int bl = (b & 15) * 2 + (b >> 4);
            int f = q * 4;
            sh[(f + 0) * 32 + bl] = v.x;
            sh[(f + 1) * 32 + bl] = v.y;
            sh[(f + 2) * 32 + bl] = v.z;
            sh[(f + 3) * 32 + bl] = v.w;
        }
        __syncthreads();
        const float* wp = wrow + (size_t)t * 512;
#pragma unroll 4
        for (int f4 = 0; f4 < 128; f4++) {
            float4 wv = *(const float4*)(wp + f4 * 4);
            const float* s0 = sh + (f4 * 4) * 32 + bb * 2;
            float2 a0 = *(const float2*)(s0);
            float2 a1 = *(const float2*)(s0 + 32);
            float2 a2 = *(const float2*)(s0 + 64);
            float2 a3 = *(const float2*)(s0 + 96);
            ax = fmaf(wv.x, a0.x, ax); ay = fmaf(wv.x, a0.y, ay);
            ax = fmaf(wv.y, a1.x, ax); ay = fmaf(wv.y, a1.y, ay);
            ax = fmaf(wv.z, a2.x, ax); ay = fmaf(wv.z, a2.y, ay);
            ax = fmaf(wv.w, a3.x, ax); ay = fmaf(wv.w, a3.y, ay);
        }
    }
    if (valid) {
        g_fc_part[((size_t)kc * 192 + n) * 32 + bb] = ax;
        g_fc_part[((size_t)kc * 192 + n) * 32 + bb + 16] = ay;
    }
}

__global__ void fc_reduce(const float* __restrict__ b1,
                          const float* __restrict__ b2,
                          float* __restrict__ out) {
    int i = blockIdx.x * 256 + threadIdx.x;
    if (i >= 6080) return;
    int n = i >> 5;                 // 0..189
    int b = i & 31;
    float s = (n < 100) ? b1[n] : b2[n - 100];
#pragma unroll
    for (int kc = 0; kc < 32; kc++)
        s += g_fc_part[((size_t)kc * 192 + n) * 32 + b];
    if (n < 100) out[b * 100 + n] = s;
    else out[3200 + b * 90 + (n - 100)] = s;
}

// ---------------------------------------------------------------------------
// Launch
// ---------------------------------------------------------------------------
extern "C" void kernel_launch(void* const* d_in, const int* in_sizes, int n_in,
                              void* d_out, int out_size) {
    const float* x       = (const float*)d_in[0];
    const float* conv_w  = (const float*)d_in[1];
    const float* conv_b  = (const float*)d_in[2];
    const float* bn_g    = (const float*)d_in[3];
    const float* bn_b    = (const float*)d_in[4];
    const float* bn_m    = (const float*)d_in[5];
    const float* bn_v    = (const float*)d_in[6];
    const float* w_ih_f0 = (const float*)d_in[7];
    const float* w_hh_f0 = (const float*)d_in[8];
    const float* b_f0    = (const float*)d_in[9];
    const float* w_ih_r0 = (const float*)d_in[10];
    const float* w_hh_r0 = (const float*)d_in[11];
    const float* b_r0    = (const float*)d_in[12];
    const float* w_ih_f1 = (const float*)d_in[13];
    const float* w_hh_f1 = (const float*)d_in[14];
    const float* b_f1    = (const float*)d_in[15];
    const float* w_ih_r1 = (const float*)d_in[16];
    const float* w_hh_r1 = (const float*)d_in[17];
    const float* b_r1    = (const float*)d_in[18];
    const float* fc1_w   = (const float*)d_in[19];
    const float* fc1_b   = (const float*)d_in[20];
    const float* fc2_w   = (const float*)d_in[21];
    const float* fc2_b   = (const float*)d_in[22];
    float* out = (float*)d_out;

    float *py, *ppf, *ppr, *ph0, *ph1;
    cudaGetSymbolAddress((void**)&py, g_y);
    cudaGetSymbolAddress((void**)&ppf, g_pre_f);
    cudaGetSymbolAddress((void**)&ppr, g_pre_r);
    cudaGetSymbolAddress((void**)&ph0, g_h0);
    cudaGetSymbolAddress((void**)&ph1, g_h1);

    cudaFuncSetAttribute(lstm_layer, cudaFuncAttributeMaxDynamicSharedMemorySize, LSTM_SMEM);
    cudaFuncSetAttribute(fc_main, cudaFuncAttributeMaxDynamicSharedMemorySize, 65536);

    // 1) conv + bn + relu
    conv_bn<<<32768, 256>>>(x, conv_w, conv_b, bn_g, bn_b, bn_m, bn_v);

    // 2) layer 0 input projections (K=256)
    dim3 gg(8, 256);
    sgemm_tn<<<gg, 256>>>(py, w_ih_f0, b_f0, ppf, 256);
    sgemm_tn<<<gg, 256>>>(py, w_ih_r0, b_r0, ppr, 256);

    // 3) layer 0 recurrence
    lstm_layer<<<64, 128, LSTM_SMEM>>>(ppf, ppr, w_hh_f0, w_hh_r0, ph0);

    // 4) layer 1 input projections (K=512)
    sgemm_tn<<<gg, 256>>>(ph0, w_ih_f1, b_f1, ppf, 512);
    sgemm_tn<<<gg, 256>>>(ph0, w_ih_r1, b_r1, ppr, 512);

    // 5) layer 1 recurrence
    lstm_layer<<<64, 128, LSTM_SMEM>>>(ppf, ppr, w_hh_f1, w_hh_r1, ph1);

    // 6) FC heads (split-k partials + deterministic reduce)
    dim3 fg(32, 12);
    fc_main<<<fg, 256, 65536>>>(ph1, fc1_w, fc2_w);
    fc_reduce<<<24, 256>>>(fc1_b, fc2_b, out);
}

// round 6
// speedup vs baseline: 1.2828x; 1.2828x over previous
#include <cuda_runtime.h>
#include <cstdint>

// ---------------------------------------------------------------------------
// Problem constants
//   B=32, T=2048, C=256, H=256, STRIDE=2, TC=1024, NC1=100, NC2=90
//   FC_IN = 2*H*TC = 524288
// ---------------------------------------------------------------------------
#define TCON 1024
typedef unsigned long long u64;

// LSTM smem: weights 16 rows x 256 = 4096 floats; h: 32 x 268 = 8576 floats
#define LSTM_SW_FLOATS 4096
#define LSTM_SH_FLOATS (32 * 268)
#define LSTM_SMEM ((LSTM_SW_FLOATS + LSTM_SH_FLOATS) * 4)

// ---------------------------------------------------------------------------
// Scratch (device globals; no runtime allocation allowed)
// ---------------------------------------------------------------------------
__device__ float g_y[32768 * 256];
__device__ float g_pre_f[33554432];     // 32768*1024
__device__ float g_pre_r[33554432];
__device__ float g_h0[16777216];        // 32768*512
__device__ float g_h1[16777216];
__device__ float g_fc_part[32 * 192 * 32];
__device__ unsigned int g_cnt[2];
__device__ unsigned int g_gen[2];

// ---------------------------------------------------------------------------
// Helpers
// ---------------------------------------------------------------------------
__device__ __forceinline__ void fma2(u64& acc, u64 a, u64 b) {
    asm("fma.rn.f32x2 %0, %1, %2, %0;" : "+l"(acc) : "l"(a), "l"(b));
}
__device__ __forceinline__ float2 u2f2(u64 v) {
    float2 r;
    asm("mov.b64 {%0,%1}, %2;" : "=f"(r.x), "=f"(r.y) : "l"(v));
    return r;
}
__device__ __forceinline__ float sigf(float x) {
    return __fdividef(1.f, 1.f + __expf(-x));
}
__device__ __forceinline__ float tanh_fast(float x) {
    return 2.f * sigf(2.f * x) - 1.f;
}
__device__ __forceinline__ unsigned ld_acq(const unsigned* p) {
    unsigned v;
    asm volatile("ld.acquire.gpu.global.u32 %0, [%1];" : "=r"(v) : "l"(p) : "memory");
    return v;
}
__device__ __forceinline__ void st_rel(unsigned* p, unsigned v) {
    asm volatile("st.release.gpu.global.u32 [%0], %1;" :: "l"(p), "r"(v) : "memory");
}
__device__ __forceinline__ void st_rlx(unsigned* p, unsigned v) {
    asm volatile("st.relaxed.gpu.global.u32 [%0], %1;" :: "l"(p), "r"(v) : "memory");
}
__device__ __forceinline__ unsigned atom_inc_acqrel(unsigned* p) {
    unsigned o;
    asm volatile("atom.add.acq_rel.gpu.global.u32 %0, [%1], 1;" : "=r"(o) : "l"(p) : "memory");
    return o;
}

// ---------------------------------------------------------------------------
// Conv1d(k=3, stride=2, pad=1) + BN(affine, eval) + ReLU
// ---------------------------------------------------------------------------
__global__ void conv_bn(const float* __restrict__ x,
                        const float* __restrict__ cw,
                        const float* __restrict__ cb,
                        const float* __restrict__ gmm,
                        const float* __restrict__ bet,
                        const float* __restrict__ mean,
                        const float* __restrict__ var) {
    int tb = blockIdx.x;
    int t = tb >> 5, b = tb & 31;
    int c = threadIdx.x;
    float w0 = cw[c * 3 + 0], w1 = cw[c * 3 + 1], w2 = cw[c * 3 + 2];
    const float* xb = x + b * 2048;
    int xi = t * 2;
    float xm1 = (xi >= 1) ? xb[xi - 1] : 0.f;
    float x0 = xb[xi];
    float xp1 = xb[xi + 1];
    float conv = fmaf(xm1, w0, fmaf(x0, w1, xp1 * w2)) + cb[c];
    float inv = gmm[c] * rsqrtf(var[c] + 1e-5f);
    float v = conv * inv + (bet[c] - mean[c] * inv);
    g_y[(size_t)tb * 256 + c] = fmaxf(v, 0.f);
}

// ---------------------------------------------------------------------------
// SGEMM (TN): C[M=32768][N=1024] = A[M][K] * B[N][K]^T + bias[N]
// ---------------------------------------------------------------------------
__global__ void __launch_bounds__(256) sgemm_tn(const float* __restrict__ A,
                                                const float* __restrict__ B,
                                                const float* __restrict__ bias,
                                                float* __restrict__ C,
                                                int K) {
    __shared__ float As[8][132];
    __shared__ float Bs[8][132];
    int bm = blockIdx.y * 128;
    int bn = blockIdx.x * 128;
    int tid = threadIdx.x;
    int tx = tid & 15, ty = tid >> 4;
    int lrow = tid >> 1;
    int lk = (tid & 1) * 4;
    const float* Ap = A + (size_t)(bm + lrow) * K + lk;
    const float* Bp = B + (size_t)(bn + lrow) * K + lk;

    float acc[8][8];
#pragma unroll
    for (int i = 0; i < 8; i++)
#pragma unroll
        for (int j = 0; j < 8; j++) acc[i][j] = 0.f;

    for (int k0 = 0; k0 < K; k0 += 8) {
        float4 av = *(const float4*)(Ap + k0);
        float4 bv = *(const float4*)(Bp + k0);
        __syncthreads();
        As[lk + 0][lrow] = av.x; As[lk + 1][lrow] = av.y;
        As[lk + 2][lrow] = av.z; As[lk + 3][lrow] = av.w;
        Bs[lk + 0][lrow] = bv.x; Bs[lk + 1][lrow] = bv.y;
        Bs[lk + 2][lrow] = bv.z; Bs[lk + 3][lrow] = bv.w;
        __syncthreads();
#pragma unroll
        for (int kk = 0; kk < 8; kk++) {
            float a[8], b[8];
            *(float4*)&a[0] = *(const float4*)&As[kk][ty * 8];
            *(float4*)&a[4] = *(const float4*)&As[kk][ty * 8 + 4];
            *(float4*)&b[0] = *(const float4*)&Bs[kk][tx * 8];
            *(float4*)&b[4] = *(const float4*)&Bs[kk][tx * 8 + 4];
#pragma unroll
            for (int i = 0; i < 8; i++)
#pragma unroll
                for (int j = 0; j < 8; j++) acc[i][j] = fmaf(a[i], b[j], acc[i][j]);
        }
    }
#pragma unroll
    for (int i = 0; i < 8; i++) {
        size_t m = (size_t)(bm + ty * 8 + i);
#pragma unroll
        for (int j = 0; j < 8; j += 4) {
            int n = bn + tx * 8 + j;
            float4 o;
            o.x = acc[i][j + 0] + bias[n + 0];
            o.y = acc[i][j + 1] + bias[n + 1];
            o.z = acc[i][j + 2] + bias[n + 2];
            o.w = acc[i][j + 3] + bias[n + 3];
            *(float4*)&C[m * 1024 + n] = o;
        }
    }
}

// ---------------------------------------------------------------------------
// BiLSTM recurrence (one layer, both directions).
// 128 blocks x 128 threads. blocks [0,64): forward, [64,128): reverse.
// Block covers j in [jg*4, jg*4+4). Warp = jj (one j), lane = batch b (0..31).
// Per thread: 1 j, 1 batch, 4 gates, all 256 k (k-paired fma.rn.f32x2).
// Weights (16 rows x 256, no duplication) in SMEM, broadcast per warp.
// h in SMEM as [b][k], row stride 268 floats (16B-aligned, conflict-free).
// Cross-block sync: release/acquire generation barrier per direction.
// ---------------------------------------------------------------------------
__global__ void __launch_bounds__(128) lstm_layer(const float* __restrict__ pre_fw,
                                                  const float* __restrict__ pre_rv,
                                                  const float* __restrict__ whh_fw,
                                                  const float* __restrict__ whh_rv,
                                                  float* __restrict__ hout) {
    extern __shared__ float smem[];
    float* sw = smem;                      // [jj*4+g][256]
    float* shh = smem + LSTM_SW_FLOATS;    // [b][268]

    const int tid = threadIdx.x;
    const int dir = blockIdx.x >> 6;
    const int jg = blockIdx.x & 63;
    const int jj = tid >> 5;               // warp id = local j
    const int b = tid & 31;                // lane = batch
    const int j = jg * 4 + jj;
    const float* whh = dir ? whh_rv : whh_fw;
    const float* pre = dir ? pre_rv : pre_fw;
    const int foff = dir ? 256 : 0;

    // Load W_hh slice: sw[(jj*4+g)*256 + k] = whh[(g*256 + j)*256 + k]
    for (int i = tid; i < 4096; i += 128) {
        int row = i >> 8;                  // jj*4+g
        int k = i & 255;
        int ljj = row >> 2, g = row & 3;
        sw[row * 256 + k] = whh[((size_t)(g * 256 + jg * 4 + ljj)) * 256 + k];
    }
    for (int i = tid; i < LSTM_SH_FLOATS; i += 128) shh[i] = 0.f;
    __syncthreads();

    const float* hrow = shh + b * 268;
    const float* wbase = sw + jj * 1024;   // 4 gate rows x 256

    unsigned* cntp = &g_cnt[dir];
    unsigned* genp = &g_gen[dir];

    float c_state = 0.f;
    int t = dir ? (TCON - 1) : 0;

    // prefetch pre-activations for step 0
    const float* pr0 = pre + ((size_t)t * 32 + b) * 1024 + j;
    float p_i = pr0[0], p_f = pr0[256], p_g = pr0[512], p_o = pr0[768];

    const int rb = tid & 31;               // repack: batch
    const int rc = tid >> 5;               // repack: k-chunk (64 floats)

    for (int step = 0; step < TCON; step++) {
        // ---- gate GEMV: acc[g] = sum_k W[g*256+j][k] * h[k][b] ----
        u64 a0 = 0ull, a1 = 0ull, a2 = 0ull, a3 = 0ull;
#pragma unroll 2
        for (int k4 = 0; k4 < 64; k4++) {
            ulonglong2 hv = *(const ulonglong2*)(hrow + k4 * 4);
            ulonglong2 w0 = *(const ulonglong2*)(wbase + k4 * 4);
            ulonglong2 w1 = *(const ulonglong2*)(wbase + 256 + k4 * 4);
            ulonglong2 w2 = *(const ulonglong2*)(wbase + 512 + k4 * 4);
            ulonglong2 w3 = *(const ulonglong2*)(wbase + 768 + k4 * 4);
            fma2(a0, w0.x, hv.x); fma2(a0, w0.y, hv.y);
            fma2(a1, w1.x, hv.x); fma2(a1, w1.y, hv.y);
            fma2(a2, w2.x, hv.x); fma2(a2, w2.y, hv.y);
            fma2(a3, w3.x, hv.x); fma2(a3, w3.y, hv.y);
        }
        float2 vi = u2f2(a0), vf = u2f2(a1), vg = u2f2(a2), vo = u2f2(a3);
        float gi = vi.x + vi.y + p_i;
        float gf = vf.x + vf.y + p_f;
        float gg = vg.x + vg.y + p_g;
        float go = vo.x + vo.y + p_o;
        float iv = sigf(gi), fv = sigf(gf), zv = tanh_fast(gg), ov = sigf(go);
        c_state = fv * c_state + iv * zv;
        float h_val = ov * tanh_fast(c_state);
        hout[((size_t)t * 32 + b) * 512 + foff + j] = h_val;

        int t_next = dir ? (t - 1) : (t + 1);
        if (step != TCON - 1) {
            // prefetch next step's pre-activations (independent of barrier)
            const float* prn = pre + ((size_t)t_next * 32 + b) * 1024 + j;
            p_i = prn[0]; p_f = prn[256]; p_g = prn[512]; p_o = prn[768];
        }

        // ---- inter-block barrier (64 blocks per direction) ----
        __threadfence();
        __syncthreads();
        if (tid == 0) {
            unsigned old = atom_inc_acqrel(cntp);
            if (old == 63u) {
                st_rlx(cntp, 0u);
                st_rel(genp, (unsigned)(step + 1));
            } else {
                while (ld_acq(genp) < (unsigned)(step + 1)) {}
            }
        }
        __syncthreads();

        // ---- repack h_t (this dir, all 256 units x 32 batches) into shh ----
        if (step != TCON - 1) {
            const float* src = hout + ((size_t)t * 32 + rb) * 512 + foff + rc * 64;
            float* dst = shh + rb * 268 + rc * 64;
#pragma unroll
            for (int q = 0; q < 16; q++) {
                float4 v = *(const float4*)(src + q * 4);
                *(float4*)(dst + q * 4) = v;
            }
        }
        __syncthreads();
        t = t_next;
    }

    // ---- epilogue: reset barrier state for next launch / graph replay ----
    if (tid == 0) {
        unsigned old = atom_inc_acqrel(cntp);
        if (old == 63u) {
            st_rlx(cntp, 0u);
            st_rlx(genp, 0u);
        }
    }
}

// ---------------------------------------------------------------------------
// FC heads (split-k partials + deterministic reduce)
// ---------------------------------------------------------------------------
__global__ void __launch_bounds__(256) fc_main(const float* __restrict__ h,
                                               const float* __restrict__ w1,
                                               const float* __restrict__ w2) {
    extern __shared__ float sh[];
    int kc = blockIdx.x;
    int grp = blockIdx.y;
    int tid = threadIdx.x;
    int nl = tid >> 4, bb = tid & 15;
    int n = grp * 16 + nl;
    bool valid = (n < 190);
    const float* wrow = valid
        ? (n < 100 ? w1 + (size_t)n * 524288 : w2 + (size_t)(n - 100) * 524288)
        : w1;

    float ax = 0.f, ay = 0.f;
    for (int tt = 0; tt < 32; tt++) {
        int t = kc * 32 + tt;
        const float* slab = h + (size_t)t * 16384;
        __syncthreads();
        for (int i = tid; i < 4096; i += 256) {
            int b = i >> 7;
            int q = i & 127;
            float4 v = *(const float4*)&slab[b * 512 + q * 4];
            int bl = (b & 15) * 2 + (b >> 4);
            int f = q * 4;
            sh[(f + 0) * 32 + bl] = v.x;
            sh[(f + 1) * 32 + bl] = v.y;
            sh[(f + 2) * 32 + bl] = v.z;
            sh[(f + 3) * 32 + bl] = v.w;
        }
        __syncthreads();
        const float* wp = wrow + (size_t)t * 512;
#pragma unroll 4
        for (int f4 = 0; f4 < 128; f4++) {
            float4 wv = *(const float4*)(wp + f4 * 4);
            const float* s0 = sh + (f4 * 4) * 32 + bb * 2;
            float2 a0 = *(const float2*)(s0);
            float2 a1 = *(const float2*)(s0 + 32);
            float2 a2 = *(const float2*)(s0 + 64);
            float2 a3 = *(const float2*)(s0 + 96);
            ax = fmaf(wv.x, a0.x, ax); ay = fmaf(wv.x, a0.y, ay);
            ax = fmaf(wv.y, a1.x, ax); ay = fmaf(wv.y, a1.y, ay);
            ax = fmaf(wv.z, a2.x, ax); ay = fmaf(wv.z, a2.y, ay);
            ax = fmaf(wv.w, a3.x, ax); ay = fmaf(wv.w, a3.y, ay);
        }
    }
    if (valid) {
        g_fc_part[((size_t)kc * 192 + n) * 32 + bb] = ax;
        g_fc_part[((size_t)kc * 192 + n) * 32 + bb + 16] = ay;
    }
}

__global__ void fc_reduce(const float* __restrict__ b1,
                          const float* __restrict__ b2,
                          float* __restrict__ out) {
    int i = blockIdx.x * 256 + threadIdx.x;
    if (i >= 6080) return;
    int n = i >> 5;
    int b = i & 31;
    float s = (n < 100) ? b1[n] : b2[n - 100];
#pragma unroll
    for (int kc = 0; kc < 32; kc++)
        s += g_fc_part[((size_t)kc * 192 + n) * 32 + b];
    if (n < 100) out[b * 100 + n] = s;
    else out[3200 + b * 90 + (n - 100)] = s;
}

// ---------------------------------------------------------------------------
// Launch
// ---------------------------------------------------------------------------
extern "C" void kernel_launch(void* const* d_in, const int* in_sizes, int n_in,
                              void* d_out, int out_size) {
    const float* x       = (const float*)d_in[0];
    const float* conv_w  = (const float*)d_in[1];
    const float* conv_b  = (const float*)d_in[2];
    const float* bn_g    = (const float*)d_in[3];
    const float* bn_b    = (const float*)d_in[4];
    const float* bn_m    = (const float*)d_in[5];
    const float* bn_v    = (const float*)d_in[6];
    const float* w_ih_f0 = (const float*)d_in[7];
    const float* w_hh_f0 = (const float*)d_in[8];
    const float* b_f0    = (const float*)d_in[9];
    const float* w_ih_r0 = (const float*)d_in[10];
    const float* w_hh_r0 = (const float*)d_in[11];
    const float* b_r0    = (const float*)d_in[12];
    const float* w_ih_f1 = (const float*)d_in[13];
    const float* w_hh_f1 = (const float*)d_in[14];
    const float* b_f1    = (const float*)d_in[15];
    const float* w_ih_r1 = (const float*)d_in[16];
    const float* w_hh_r1 = (const float*)d_in[17];
    const float* b_r1    = (const float*)d_in[18];
    const float* fc1_w   = (const float*)d_in[19];
    const float* fc1_b   = (const float*)d_in[20];
    const float* fc2_w   = (const float*)d_in[21];
    const float* fc2_b   = (const float*)d_in[22];
    float* out = (float*)d_out;

    float *py, *ppf, *ppr, *ph0, *ph1;
    cudaGetSymbolAddress((void**)&py, g_y);
    cudaGetSymbolAddress((void**)&ppf, g_pre_f);
    cudaGetSymbolAddress((void**)&ppr, g_pre_r);
    cudaGetSymbolAddress((void**)&ph0, g_h0);
    cudaGetSymbolAddress((void**)&ph1, g_h1);

    cudaFuncSetAttribute(lstm_layer, cudaFuncAttributeMaxDynamicSharedMemorySize, LSTM_SMEM);
    cudaFuncSetAttribute(fc_main, cudaFuncAttributeMaxDynamicSharedMemorySize, 65536);

    // 1) conv + bn + relu
    conv_bn<<<32768, 256>>>(x, conv_w, conv_b, bn_g, bn_b, bn_m, bn_v);

    // 2) layer 0 input projections (K=256)
    dim3 gg(8, 256);
    sgemm_tn<<<gg, 256>>>(py, w_ih_f0, b_f0, ppf, 256);
    sgemm_tn<<<gg, 256>>>(py, w_ih_r0, b_r0, ppr, 256);

    // 3) layer 0 recurrence
    lstm_layer<<<128, 128, LSTM_SMEM>>>(ppf, ppr, w_hh_f0, w_hh_r0, ph0);

    // 4) layer 1 input projections (K=512)
    sgemm_tn<<<gg, 256>>>(ph0, w_ih_f1, b_f1, ppf, 512);
    sgemm_tn<<<gg, 256>>>(ph0, w_ih_r1, b_r1, ppr, 512);

    // 5) layer 1 recurrence
    lstm_layer<<<128, 128, LSTM_SMEM>>>(ppf, ppr, w_hh_f1, w_hh_r1, ph1);

    // 6) FC heads
    dim3 fg(32, 12);
    fc_main<<<fg, 256, 65536>>>(ph1, fc1_w, fc2_w);
    fc_reduce<<<24, 256>>>(fc1_b, fc2_b, out);
}